// round 14
// baseline (speedup 1.0000x reference)
#include <cuda_runtime.h>
#include <cuda_fp16.h>
#include <cstdint>

#define B_   64
#define NQ   512
#define NV   1024
#define QD   768
#define VD   512
#define HIDD 512

// ---------------- scratch (device globals; no allocation allowed) ----------
__device__ __align__(16) float g_a[QD];
__device__ __align__(16) float g_c[VD];
__device__ float g_s0;
__device__ float g_rq[B_ * NQ];
__device__ float g_cv[B_ * NV];
__device__ __align__(16) __half g_Qf[(size_t)B_ * NQ * QD];
__device__ __align__(16) __half g_Vf[(size_t)B_ * NV * VD];
__device__ __align__(16) __half g_MTf[VD * QD];
__device__ __align__(16) __half g_QMf[(size_t)B_ * NQ * VD];
__device__ __align__(16) __half g_E[(size_t)B_ * NQ * NV];
// atomic accumulators (zeroed each call by compute_ac): [dr(B*NQ) | dc(B*NV) | wv(B*NV)]
#define ZN (B_ * NQ + 2 * B_ * NV)
#define NOUT (B_ * VD + B_ * QD)
__device__ float g_zero[ZN];
__device__ float g_wq[B_ * NQ];

// ---------------- PTX helpers (sm_80+ features only) ------------------------
__device__ __forceinline__ uint32_t smem_u32(const void* p) {
    uint32_t a;
    asm("{ .reg .u64 t; cvta.to.shared.u64 t, %1; cvt.u32.u64 %0, t; }" : "=r"(a) : "l"(p));
    return a;
}
__device__ __forceinline__ void cp16(uint32_t s, const void* g) {
    asm volatile("cp.async.cg.shared.global [%0], [%1], 16;" :: "r"(s), "l"(g));
}
__device__ __forceinline__ void cp_commit() { asm volatile("cp.async.commit_group;" ::: "memory"); }
__device__ __forceinline__ void cp_wait1()  { asm volatile("cp.async.wait_group 1;" ::: "memory"); }

__device__ __forceinline__ void ldm4(uint32_t a, uint32_t& r0, uint32_t& r1,
                                     uint32_t& r2, uint32_t& r3) {
    asm volatile("ldmatrix.sync.aligned.m8n8.x4.shared.b16 {%0,%1,%2,%3}, [%4];"
                 : "=r"(r0), "=r"(r1), "=r"(r2), "=r"(r3) : "r"(a));
}
__device__ __forceinline__ void mma16816(float& c0, float& c1, float& c2, float& c3,
                                         uint32_t a0, uint32_t a1, uint32_t a2, uint32_t a3,
                                         uint32_t b0, uint32_t b1) {
    asm volatile("mma.sync.aligned.m16n8k16.row.col.f32.f16.f16.f32 "
                 "{%0,%1,%2,%3}, {%4,%5,%6,%7}, {%8,%9}, {%0,%1,%2,%3};"
                 : "+f"(c0), "+f"(c1), "+f"(c2), "+f"(c3)
                 : "r"(a0), "r"(a1), "r"(a2), "r"(a3), "r"(b0), "r"(b1));
}
// HW tanh (sm_75+ MUFU.TANH) then exp
__device__ __forceinline__ float exp_tanh(float y) {
    float t;
    asm("tanh.approx.f32 %0, %1;" : "=f"(t) : "f"(y));
    return __expf(t);
}

// ------- precompute a, c, s0 + zero atomic accumulators AND the output -------
__global__ void compute_ac(const float* __restrict__ Wq, const float* __restrict__ Wv,
                           const float* __restrict__ bq, const float* __restrict__ bv,
                           float* __restrict__ out) {
    int t = blockIdx.x * 1024 + threadIdx.x;
    if (t < ZN) g_zero[t] = 0.f;
    if (t < NOUT) out[t] = 0.f;
    if (t < QD) {
        float s = 0.f;
        for (int h = 0; h < HIDD; h++) s += Wq[h * QD + t] * bv[h];
        g_a[t] = s;
    } else if (t < QD + VD) {
        int e = t - QD;
        float s = 0.f;
        for (int h = 0; h < HIDD; h++) s += Wv[h * VD + e] * bq[h];
        g_c[e] = s;
    } else if (t == QD + VD) {
        float s = 0.f;
        for (int h = 0; h < HIDD; h++) s += bq[h] * bv[h];
        g_s0 = s;
    }
}

// ---------------- prep kernel: Q cvt+dot, V cvt+dot, MT GEMM (one launch) ----
template <int K, int NF4, bool ADD_S0>
__device__ __forceinline__ void cvt_dot_row(const float* __restrict__ X,
                                            __half* __restrict__ Xf,
                                            const float* __restrict__ vec,
                                            float* __restrict__ out,
                                            int row, int lane) {
    const float4* xr = (const float4*)(X + (size_t)row * K);
    const float4* vr = (const float4*)vec;
    __half2* hr = (__half2*)(Xf + (size_t)row * K);
    float s = 0.f;
#pragma unroll
    for (int j = 0; j < NF4; j++) {
        int idx = lane + j * 32;
        float4 v = xr[idx];
        float4 a = vr[idx];
        s += v.x * a.x + v.y * a.y + v.z * a.z + v.w * a.w;
        hr[2 * idx]     = __floats2half2_rn(v.x, v.y);
        hr[2 * idx + 1] = __floats2half2_rn(v.z, v.w);
    }
#pragma unroll
    for (int o = 16; o; o >>= 1) s += __shfl_xor_sync(0xffffffffu, s, o);
    if (!lane) out[row] = s + (ADD_S0 ? g_s0 : 0.f);
}

// MT tile: MT[v,q] = sum_h Wv[h,v]*Wq[h,q]; A=Wv [HIDD,VD], B=Wq [HIDD,QD], fp16 out
__device__ void mt_tile(const float* __restrict__ A, const float* __restrict__ B,
                        __half* __restrict__ C, int m0, int n0) {
    const int BK = 8;
    __shared__ float As[BK][128 + 4];
    __shared__ float Bs[BK][128 + 4];
    const int tid = threadIdx.x;
    const int tx = tid & 15, ty = tid >> 4;
    float acc[8][8];
#pragma unroll
    for (int i = 0; i < 8; i++)
#pragma unroll
        for (int j = 0; j < 8; j++) acc[i][j] = 0.f;
    for (int k0 = 0; k0 < HIDD; k0 += BK) {
        {
            int k = tid >> 5, m4 = (tid & 31) * 4;
            *(float4*)&As[k][m4] = *(const float4*)&A[(size_t)(k0 + k) * VD + m0 + m4];
        }
        {
            int k = tid >> 5, n4 = (tid & 31) * 4;
            *(float4*)&Bs[k][n4] = *(const float4*)&B[(size_t)(k0 + k) * QD + n0 + n4];
        }
        __syncthreads();
#pragma unroll
        for (int k = 0; k < BK; k++) {
            float4 a0 = *(const float4*)&As[k][ty * 8];
            float4 a1 = *(const float4*)&As[k][ty * 8 + 4];
            float4 b0 = *(const float4*)&Bs[k][tx * 8];
            float4 b1 = *(const float4*)&Bs[k][tx * 8 + 4];
            float ar[8] = {a0.x, a0.y, a0.z, a0.w, a1.x, a1.y, a1.z, a1.w};
            float br[8] = {b0.x, b0.y, b0.z, b0.w, b1.x, b1.y, b1.z, b1.w};
#pragma unroll
            for (int i = 0; i < 8; i++)
#pragma unroll
                for (int j = 0; j < 8; j++) acc[i][j] += ar[i] * br[j];
        }
        __syncthreads();
    }
#pragma unroll
    for (int i = 0; i < 8; i++) {
        int m = m0 + ty * 8 + i;
        __half2* cptr = (__half2*)&C[(size_t)m * QD + n0 + tx * 8];
#pragma unroll
        for (int j = 0; j < 4; j++)
            cptr[j] = __floats2half2_rn(acc[i][2 * j], acc[i][2 * j + 1]);
    }
}

#define QBLOCKS (B_ * NQ / 8)   // 4096
#define VBLOCKS (B_ * NV / 8)   // 8192
#define MTTILES ((VD / 128) * (QD / 128))  // 4*6 = 24

__global__ __launch_bounds__(256)
void prep_kernel(const float* __restrict__ Q, const float* __restrict__ V,
                 const float* __restrict__ Wq, const float* __restrict__ Wv) {
    int lane = threadIdx.x & 31;
    if (blockIdx.x < QBLOCKS) {
        int row = blockIdx.x * 8 + (threadIdx.x >> 5);
        cvt_dot_row<QD, QD / 128, true>(Q, g_Qf, g_a, g_rq, row, lane);
    } else if (blockIdx.x < QBLOCKS + VBLOCKS) {
        int row = (blockIdx.x - QBLOCKS) * 8 + (threadIdx.x >> 5);
        cvt_dot_row<VD, VD / 128, false>(V, g_Vf, g_c, g_cv, row, lane);
    } else {
        int t = blockIdx.x - QBLOCKS - VBLOCKS;           // 0..23
        int mt = t / (QD / 128), nt = t % (QD / 128);
        mt_tile(Wv, Wq, g_MTf, mt * 128, nt * 128);
    }
}

// ---------------- mma.sync fp16 GEMM, 128x128x32, 3-stage, 2 CTAs/SM ---------
#define STG_BYTES 20480   // A tile 128*80 + B tile 128*80
#define SMEM_DYN  (3 * STG_BYTES)

__device__ __forceinline__ void load_stage(uint32_t sb, const __half* pa,
                                           const __half* pb, int m0, int n0,
                                           int kk, int K, int r, int c) {
    const __half* ga = pa + (size_t)(m0 + r) * K + kk + c * 8;
    cp16(sb + r * 80 + c * 16, ga);
    cp16(sb + (r + 64) * 80 + c * 16, ga + (size_t)64 * K);
    const __half* gb = pb + (size_t)(n0 + r) * K + kk + c * 8;
    cp16(sb + 10240 + r * 80 + c * 16, gb);
    cp16(sb + 10240 + (r + 64) * 80 + c * 16, gb + (size_t)64 * K);
}

// EPI=false: C = fp16(acc).  EPI=true: E=fp16(exp(tanh(acc+rq+cv))) + atomic row/col sums.
template <bool EPI>
__global__ __launch_bounds__(256, 2)
void mma_gemm(const __half* __restrict__ A, const __half* __restrict__ B,
              int K, long long sA, long long sB,
              __half* __restrict__ C, int ldc,
              __half* __restrict__ E, const float* __restrict__ rq, const float* __restrict__ cv,
              float* __restrict__ dr, float* __restrict__ dc) {
    extern __shared__ __align__(128) uint8_t smbuf[];
    const int tid = threadIdx.x, lid = tid & 31, wid = tid >> 5;
    const int wm = wid >> 2, wn = wid & 3;   // 2 x 4 warp grid
    const int m0 = blockIdx.y * 128, n0 = blockIdx.x * 128, bz = blockIdx.z;
    A += (size_t)bz * sA;
    B += (size_t)bz * sB;

    const int T = K / 32;
    const int lr = tid >> 2, lc = tid & 3;   // loader row/chunk

    float acc[4][4][4] = {};
    uint32_t sb0 = smem_u32(smbuf);

#pragma unroll
    for (int i = 0; i < 2; i++) {
        load_stage(sb0 + i * STG_BYTES, A, B, m0, n0, i * 32, K, lr, lc);
        cp_commit();
    }

    for (int i = 0; i < T; i++) {
        cp_wait1();
        __syncthreads();
        if (i + 2 < T) {
            int s = (i + 2) % 3;
            load_stage(sb0 + s * STG_BYTES, A, B, m0, n0, (i + 2) * 32, K, lr, lc);
        }
        cp_commit();
        uint32_t sb = sb0 + (i % 3) * STG_BYTES;

#pragma unroll
        for (int ks = 0; ks < 2; ks++) {
            uint32_t Af[4][4], Bf[2][4];
#pragma unroll
            for (int mf = 0; mf < 4; mf++) {
                int row = wm * 64 + mf * 16 + (lid & 15);
                int ch = ks * 2 + (lid >> 4);
                ldm4(sb + row * 80 + ch * 16,
                     Af[mf][0], Af[mf][1], Af[mf][2], Af[mf][3]);
            }
#pragma unroll
            for (int np = 0; np < 2; np++) {
                int g = lid >> 3;
                int row = wn * 32 + np * 16 + ((g >> 1) << 3) + (lid & 7);
                int ch = ks * 2 + (g & 1);
                ldm4(sb + 10240 + row * 80 + ch * 16,
                     Bf[np][0], Bf[np][1], Bf[np][2], Bf[np][3]);
            }
#pragma unroll
            for (int mf = 0; mf < 4; mf++)
#pragma unroll
                for (int nf = 0; nf < 4; nf++) {
                    uint32_t b0 = Bf[nf >> 1][(nf & 1) * 2];
                    uint32_t b1 = Bf[nf >> 1][(nf & 1) * 2 + 1];
                    mma16816(acc[mf][nf][0], acc[mf][nf][1], acc[mf][nf][2], acc[mf][nf][3],
                             Af[mf][0], Af[mf][1], Af[mf][2], Af[mf][3],
                             b0, b1);
                }
        }
    }

    // epilogue
    const int gr = lid >> 2, gc = (lid & 3) * 2;
    if (!EPI) {
#pragma unroll
        for (int mf = 0; mf < 4; mf++) {
            int m = m0 + wm * 64 + mf * 16 + gr;
#pragma unroll
            for (int nf = 0; nf < 4; nf++) {
                int n = n0 + wn * 32 + nf * 8 + gc;
                *(__half2*)(C + (size_t)m * ldc + n) =
                    __floats2half2_rn(acc[mf][nf][0], acc[mf][nf][1]);
                *(__half2*)(C + (size_t)(m + 8) * ldc + n) =
                    __floats2half2_rn(acc[mf][nf][2], acc[mf][nf][3]);
            }
        }
    } else {
        float colp[4][2] = {};
        float rowp0[4], rowp1[4];
#pragma unroll
        for (int mf = 0; mf < 4; mf++) {
            int m = m0 + wm * 64 + mf * 16 + gr;
            float r0v = rq[bz * NQ + m], r1v = rq[bz * NQ + m + 8];
            float s0 = 0.f, s1 = 0.f;
#pragma unroll
            for (int nf = 0; nf < 4; nf++) {
                int n = n0 + wn * 32 + nf * 8 + gc;
                float cv0 = cv[bz * NV + n], cv1 = cv[bz * NV + n + 1];
                float e00 = exp_tanh(acc[mf][nf][0] + r0v + cv0);
                float e01 = exp_tanh(acc[mf][nf][1] + r0v + cv1);
                float e10 = exp_tanh(acc[mf][nf][2] + r1v + cv0);
                float e11 = exp_tanh(acc[mf][nf][3] + r1v + cv1);
                size_t e0 = (size_t)bz * NQ * NV + (size_t)m * NV + n;
                *(__half2*)(E + e0) = __floats2half2_rn(e00, e01);
                *(__half2*)(E + e0 + (size_t)8 * NV) = __floats2half2_rn(e10, e11);
                s0 += e00 + e01;
                s1 += e10 + e11;
                colp[nf][0] += e00 + e10;
                colp[nf][1] += e01 + e11;
            }
            rowp0[mf] = s0;
            rowp1[mf] = s1;
        }
#pragma unroll
        for (int mf = 0; mf < 4; mf++) {
            float s0 = rowp0[mf], s1 = rowp1[mf];
            s0 += __shfl_xor_sync(0xffffffffu, s0, 1);
            s0 += __shfl_xor_sync(0xffffffffu, s0, 2);
            s1 += __shfl_xor_sync(0xffffffffu, s1, 1);
            s1 += __shfl_xor_sync(0xffffffffu, s1, 2);
            if ((lid & 3) == 0) {
                int m = m0 + wm * 64 + mf * 16 + gr;
                atomicAdd(dr + bz * NQ + m, s0);
                atomicAdd(dr + bz * NQ + m + 8, s1);
            }
        }
#pragma unroll
        for (int nf = 0; nf < 4; nf++)
#pragma unroll
            for (int t = 0; t < 2; t++) {
                float s = colp[nf][t];
                s += __shfl_xor_sync(0xffffffffu, s, 4);
                s += __shfl_xor_sync(0xffffffffu, s, 8);
                s += __shfl_xor_sync(0xffffffffu, s, 16);
                colp[nf][t] = s;
            }
        if (lid < 4) {
#pragma unroll
            for (int nf = 0; nf < 4; nf++) {
                int n = n0 + wn * 32 + nf * 8 + gc;
                atomicAdd(dc + bz * NV + n, colp[nf][0]);
                atomicAdd(dc + bz * NV + n + 1, colp[nf][1]);
            }
        }
    }
}

// ---------------- fused wq + wv: single pass over E --------------------------
__global__ __launch_bounds__(256)
void wqwv_kernel(const float* __restrict__ dr, const float* __restrict__ dc,
                 float* __restrict__ wv) {
    __shared__ float2 sdc[NV / 2];
    int b = blockIdx.y, q0 = blockIdx.x * 128;
    int tid = threadIdx.x, w = tid >> 5, lane = tid & 31;
    for (int i = tid; i < NV / 2; i += 256) {
        sdc[i].x = 1.f / dc[b * NV + 2 * i];
        sdc[i].y = 1.f / dc[b * NV + 2 * i + 1];
    }
    __syncthreads();

    float colacc[32] = {};
#pragma unroll 1
    for (int r = 0; r < 16; r++) {
        int q = q0 + w * 16 + r;
        const __half2* row = (const __half2*)(g_E + (size_t)(b * NQ + q) * NV);
        float idr = 1.f / dr[b * NQ + q];
        float s = 0.f;
#pragma unroll
        for (int j = 0; j < 16; j++) {
            int idx = lane + j * 32;
            float2 v = __half22float2(row[idx]);
            float2 d = sdc[idx];
            s += v.x * d.x + v.y * d.y;
            colacc[2 * j]     += v.x * idr;
            colacc[2 * j + 1] += v.y * idr;
        }
#pragma unroll
        for (int o = 16; o; o >>= 1) s += __shfl_xor_sync(0xffffffffu, s, o);
        if (!lane) g_wq[b * NQ + q] = s;
    }
#pragma unroll
    for (int j = 0; j < 16; j++) {
        int idx = lane + j * 32;
        atomicAdd(wv + b * NV + 2 * idx, colacc[2 * j]);
        atomicAdd(wv + b * NV + 2 * idx + 1, colacc[2 * j + 1]);
    }
}

// ------------- pools: v_hat and q_hat partials straight into out -------------
__global__ __launch_bounds__(768)
void pools_kernel(const float* __restrict__ wv, float* __restrict__ out) {
    int b = blockIdx.x, y = blockIdx.y, d = threadIdx.x;
    if (y < 4) {
        if (d < VD) {
            const __half* Vb = g_Vf + (size_t)b * NV * VD + (size_t)y * (NV / 4) * VD;
            const float* w = wv + b * NV + y * (NV / 4);
            float s = 0.f;
#pragma unroll 4
            for (int v = 0; v < NV / 4; v++) s += w[v] * __half2float(Vb[(size_t)v * VD + d]);
            atomicAdd(out + b * VD + d, s);
        }
    } else {
        int part = y - 4;
        const __half* Qb = g_Qf + (size_t)b * NQ * QD + (size_t)part * (NQ / 4) * QD;
        const float* w = g_wq + b * NQ + part * (NQ / 4);
        float s = 0.f;
#pragma unroll 4
        for (int q = 0; q < NQ / 4; q++) s += w[q] * __half2float(Qb[(size_t)q * QD + d]);
        atomicAdd(out + B_ * VD + b * QD + d, s);
    }
}

// ---------------- launch -----------------------------------------------------
extern "C" void kernel_launch(void* const* d_in, const int* in_sizes, int n_in,
                              void* d_out, int out_size) {
    const float* V  = (const float*)d_in[0];
    const float* Q  = (const float*)d_in[1];
    const float* Wq = (const float*)d_in[2];
    const float* bq = (const float*)d_in[3];
    const float* Wv = (const float*)d_in[4];
    const float* bv = (const float*)d_in[5];
    float* out = (float*)d_out;

    float *pz, *prq, *pcv;
    __half *pQf, *pVf, *pMTf, *pQMf, *pE;
    cudaGetSymbolAddress((void**)&prq, g_rq);
    cudaGetSymbolAddress((void**)&pcv, g_cv);
    cudaGetSymbolAddress((void**)&pz, g_zero);
    cudaGetSymbolAddress((void**)&pE, g_E);
    cudaGetSymbolAddress((void**)&pQf, g_Qf);
    cudaGetSymbolAddress((void**)&pVf, g_Vf);
    cudaGetSymbolAddress((void**)&pMTf, g_MTf);
    cudaGetSymbolAddress((void**)&pQMf, g_QMf);
    float* pdr = pz;
    float* pdc = pz + B_ * NQ;
    float* pwv = pz + B_ * NQ + B_ * NV;

    cudaFuncSetAttribute((const void*)mma_gemm<false>,
                         cudaFuncAttributeMaxDynamicSharedMemorySize, SMEM_DYN);
    cudaFuncSetAttribute((const void*)mma_gemm<true>,
                         cudaFuncAttributeMaxDynamicSharedMemorySize, SMEM_DYN);

    // 1) a, c, s0 + zero accumulators and output
    compute_ac<<<(ZN + 1023) / 1024, 1024>>>(Wq, Wv, bq, bv, out);
    // 2) prep: Q/V convert+dot and MT GEMM in one launch
    prep_kernel<<<QBLOCKS + VBLOCKS + MTTILES, 256>>>(Q, V, Wq, Wv);
    // 3) QM = Q @ MT^T
    mma_gemm<false><<<dim3(VD / 128, (B_ * NQ) / 128, 1), 256, SMEM_DYN>>>(
        pQf, pMTf, QD, 0, 0, pQMf, VD, nullptr, nullptr, nullptr, nullptr, nullptr);
    // 4) E = exp(tanh(QM @ V^T + rq + cv)) -> fp16, + fused row/col sums  (4th: profiled)
    mma_gemm<true><<<dim3(NV / 128, NQ / 128, B_), 256, SMEM_DYN>>>(
        pQMf, pVf, VD, (long long)NQ * VD, (long long)NV * VD,
        nullptr, 0, pE, prq, pcv, pdr, pdc);
    // 5) fused wq + wv (one pass over E)
    wqwv_kernel<<<dim3(NQ / 128, B_), 256>>>(pdr, pdc, pwv);
    // 6) pools -> out directly
    pools_kernel<<<dim3(B_, 8), 768>>>(pwv, out);
}

// round 15
// speedup vs baseline: 1.0150x; 1.0150x over previous
#include <cuda_runtime.h>
#include <cuda_fp16.h>
#include <cstdint>

#define B_   64
#define NQ   512
#define NV   1024
#define QD   768
#define VD   512
#define HIDD 512

// ---------------- scratch (device globals; no allocation allowed) ----------
__device__ __align__(16) float g_a[QD];
__device__ __align__(16) float g_c[VD];
__device__ float g_s0;
__device__ float g_rq[B_ * NQ];
__device__ float g_cv[B_ * NV];
__device__ __align__(16) __half g_Qf[(size_t)B_ * NQ * QD];
__device__ __align__(16) __half g_Vf[(size_t)B_ * NV * VD];
__device__ __align__(16) __half g_MTf[VD * QD];
__device__ __align__(16) __half g_QMf[(size_t)B_ * NQ * VD];
__device__ __align__(16) __half g_E[(size_t)B_ * NQ * NV];
// atomic accumulators (zeroed each call by compute_ac): [dr(B*NQ) | dc(B*NV) | wv(B*NV)]
#define ZN (B_ * NQ + 2 * B_ * NV)
#define NOUT (B_ * VD + B_ * QD)
__device__ float g_zero[ZN];
__device__ float g_wq[B_ * NQ];

// ---------------- PTX helpers (sm_80+ features only) ------------------------
__device__ __forceinline__ uint32_t smem_u32(const void* p) {
    uint32_t a;
    asm("{ .reg .u64 t; cvta.to.shared.u64 t, %1; cvt.u32.u64 %0, t; }" : "=r"(a) : "l"(p));
    return a;
}
__device__ __forceinline__ void cp16(uint32_t s, const void* g) {
    asm volatile("cp.async.cg.shared.global [%0], [%1], 16;" :: "r"(s), "l"(g));
}
__device__ __forceinline__ void cp_commit() { asm volatile("cp.async.commit_group;" ::: "memory"); }
__device__ __forceinline__ void cp_wait1()  { asm volatile("cp.async.wait_group 1;" ::: "memory"); }

__device__ __forceinline__ void ldm4(uint32_t a, uint32_t& r0, uint32_t& r1,
                                     uint32_t& r2, uint32_t& r3) {
    asm volatile("ldmatrix.sync.aligned.m8n8.x4.shared.b16 {%0,%1,%2,%3}, [%4];"
                 : "=r"(r0), "=r"(r1), "=r"(r2), "=r"(r3) : "r"(a));
}
__device__ __forceinline__ void mma16816(float& c0, float& c1, float& c2, float& c3,
                                         uint32_t a0, uint32_t a1, uint32_t a2, uint32_t a3,
                                         uint32_t b0, uint32_t b1) {
    asm volatile("mma.sync.aligned.m16n8k16.row.col.f32.f16.f16.f32 "
                 "{%0,%1,%2,%3}, {%4,%5,%6,%7}, {%8,%9}, {%0,%1,%2,%3};"
                 : "+f"(c0), "+f"(c1), "+f"(c2), "+f"(c3)
                 : "r"(a0), "r"(a1), "r"(a2), "r"(a3), "r"(b0), "r"(b1));
}
// HW tanh (sm_75+ MUFU.TANH) then exp
__device__ __forceinline__ float exp_tanh(float y) {
    float t;
    asm("tanh.approx.f32 %0, %1;" : "=f"(t) : "f"(y));
    return __expf(t);
}

// ------- precompute a, c, s0 + zero atomic accumulators AND the output -------
__global__ void compute_ac(const float* __restrict__ Wq, const float* __restrict__ Wv,
                           const float* __restrict__ bq, const float* __restrict__ bv,
                           float* __restrict__ out) {
    int t = blockIdx.x * 1024 + threadIdx.x;
    if (t < ZN) g_zero[t] = 0.f;
    if (t < NOUT) out[t] = 0.f;
    if (t < QD) {
        float s = 0.f;
        for (int h = 0; h < HIDD; h++) s += Wq[h * QD + t] * bv[h];
        g_a[t] = s;
    } else if (t < QD + VD) {
        int e = t - QD;
        float s = 0.f;
        for (int h = 0; h < HIDD; h++) s += Wv[h * VD + e] * bq[h];
        g_c[e] = s;
    } else if (t == QD + VD) {
        float s = 0.f;
        for (int h = 0; h < HIDD; h++) s += bq[h] * bv[h];
        g_s0 = s;
    }
}

// ---------------- fused fp32->fp16 convert + row-dot (Q and V in ONE launch) --
template <int K, int NF4, bool ADD_S0>
__device__ __forceinline__ void cvt_dot_row(const float* __restrict__ X,
                                            __half* __restrict__ Xf,
                                            const float* __restrict__ vec,
                                            float* __restrict__ out,
                                            int row, int lane) {
    const float4* xr = (const float4*)(X + (size_t)row * K);
    const float4* vr = (const float4*)vec;
    __half2* hr = (__half2*)(Xf + (size_t)row * K);
    float s = 0.f;
#pragma unroll
    for (int j = 0; j < NF4; j++) {
        int idx = lane + j * 32;
        float4 v = xr[idx];
        float4 a = vr[idx];
        s += v.x * a.x + v.y * a.y + v.z * a.z + v.w * a.w;
        hr[2 * idx]     = __floats2half2_rn(v.x, v.y);
        hr[2 * idx + 1] = __floats2half2_rn(v.z, v.w);
    }
#pragma unroll
    for (int o = 16; o; o >>= 1) s += __shfl_xor_sync(0xffffffffu, s, o);
    if (!lane) out[row] = s + (ADD_S0 ? g_s0 : 0.f);
}

#define QBLOCKS (B_ * NQ / 8)   // 4096
#define VBLOCKS (B_ * NV / 8)   // 8192

__global__ void fuse_both(const float* __restrict__ Q, const float* __restrict__ V) {
    int lane = threadIdx.x & 31;
    if (blockIdx.x < QBLOCKS) {
        int row = blockIdx.x * 8 + (threadIdx.x >> 5);
        cvt_dot_row<QD, QD / 128, true>(Q, g_Qf, g_a, g_rq, row, lane);
    } else {
        int row = (blockIdx.x - QBLOCKS) * 8 + (threadIdx.x >> 5);
        cvt_dot_row<VD, VD / 128, false>(V, g_Vf, g_c, g_cv, row, lane);
    }
}

// ---------------- fp32 GEMM -> fp16 out (tiny MT = Wv^T Wq) ------------------
__global__ __launch_bounds__(256)
void gemm_tn_kernel(const float* __restrict__ A, const float* __restrict__ B,
                    __half* __restrict__ C, int K, int lda, int ldb, int ldc) {
    const int BM = 128, BN = 128, BK = 8;
    const int m0 = blockIdx.y * BM, n0 = blockIdx.x * BN;
    __shared__ float As[BK][BM + 4];
    __shared__ float Bs[BK][BN + 4];
    const int tid = threadIdx.x;
    const int tx = tid & 15, ty = tid >> 4;
    float acc[8][8];
#pragma unroll
    for (int i = 0; i < 8; i++)
#pragma unroll
        for (int j = 0; j < 8; j++) acc[i][j] = 0.f;
    for (int k0 = 0; k0 < K; k0 += BK) {
        {
            int k = tid >> 5, m4 = (tid & 31) * 4;
            *(float4*)&As[k][m4] = *(const float4*)&A[(size_t)(k0 + k) * lda + m0 + m4];
        }
        {
            int k = tid >> 5, n4 = (tid & 31) * 4;
            *(float4*)&Bs[k][n4] = *(const float4*)&B[(size_t)(k0 + k) * ldb + n0 + n4];
        }
        __syncthreads();
#pragma unroll
        for (int k = 0; k < BK; k++) {
            float4 a0 = *(const float4*)&As[k][ty * 8];
            float4 a1 = *(const float4*)&As[k][ty * 8 + 4];
            float4 b0 = *(const float4*)&Bs[k][tx * 8];
            float4 b1 = *(const float4*)&Bs[k][tx * 8 + 4];
            float ar[8] = {a0.x, a0.y, a0.z, a0.w, a1.x, a1.y, a1.z, a1.w};
            float br[8] = {b0.x, b0.y, b0.z, b0.w, b1.x, b1.y, b1.z, b1.w};
#pragma unroll
            for (int i = 0; i < 8; i++)
#pragma unroll
                for (int j = 0; j < 8; j++) acc[i][j] += ar[i] * br[j];
        }
        __syncthreads();
    }
#pragma unroll
    for (int i = 0; i < 8; i++) {
        int m = m0 + ty * 8 + i;
        __half2* cptr = (__half2*)&C[(size_t)m * ldc + n0 + tx * 8];
#pragma unroll
        for (int j = 0; j < 4; j++)
            cptr[j] = __floats2half2_rn(acc[i][2 * j], acc[i][2 * j + 1]);
    }
}

// ======== GEMM1: 64x128 tile, 128 threads, 4 CTAs/SM (barrier-granularity exp)
#define STG1_A (64 * 80)          // 5120
#define STG1_BYTES (64 * 80 + 128 * 80)   // 15360
#define SMEM1_DYN (3 * STG1_BYTES)        // 46080

__device__ __forceinline__ void load_stage1(uint32_t sb, const __half* pa,
                                            const __half* pb, int m0, int n0,
                                            int kk, int K, int tid) {
    // A: 64 rows x 64B (2 cp16/thread), B: 128 rows x 64B (4 cp16/thread)
    int ra = tid >> 1, ca = (tid & 1) * 2;
    const __half* ga = pa + (size_t)(m0 + ra) * K + kk + ca * 8;
    cp16(sb + ra * 80 + ca * 16, ga);
    cp16(sb + ra * 80 + (ca + 1) * 16, ga + 8);
    const __half* gb = pb + (size_t)(n0 + tid) * K + kk;
    uint32_t db = sb + STG1_A + tid * 80;
#pragma unroll
    for (int c = 0; c < 4; c++) cp16(db + c * 16, gb + c * 8);
}

__global__ __launch_bounds__(128, 4)
void mma_gemm1(const __half* __restrict__ A, const __half* __restrict__ B,
               __half* __restrict__ C) {
    extern __shared__ __align__(128) uint8_t smbuf[];
    const int tid = threadIdx.x, lid = tid & 31, wn = tid >> 5;  // 4 warps over N
    const int m0 = blockIdx.y * 64, n0 = blockIdx.x * 128;
    const int K = QD, T = K / 32;

    float acc[4][4][4] = {};
    uint32_t sb0 = smem_u32(smbuf);

#pragma unroll
    for (int i = 0; i < 2; i++) {
        load_stage1(sb0 + i * STG1_BYTES, A, B, m0, n0, i * 32, K, tid);
        cp_commit();
    }

    for (int i = 0; i < T; i++) {
        cp_wait1();
        __syncthreads();
        if (i + 2 < T) {
            int s = (i + 2) % 3;
            load_stage1(sb0 + s * STG1_BYTES, A, B, m0, n0, (i + 2) * 32, K, tid);
        }
        cp_commit();
        uint32_t sb = sb0 + (i % 3) * STG1_BYTES;

#pragma unroll
        for (int ks = 0; ks < 2; ks++) {
            uint32_t Af[4][4], Bf[2][4];
#pragma unroll
            for (int mf = 0; mf < 4; mf++) {
                int row = mf * 16 + (lid & 15);
                int ch = ks * 2 + (lid >> 4);
                ldm4(sb + row * 80 + ch * 16,
                     Af[mf][0], Af[mf][1], Af[mf][2], Af[mf][3]);
            }
#pragma unroll
            for (int np = 0; np < 2; np++) {
                int g = lid >> 3;
                int row = wn * 32 + np * 16 + ((g >> 1) << 3) + (lid & 7);
                int ch = ks * 2 + (g & 1);
                ldm4(sb + STG1_A + row * 80 + ch * 16,
                     Bf[np][0], Bf[np][1], Bf[np][2], Bf[np][3]);
            }
#pragma unroll
            for (int mf = 0; mf < 4; mf++)
#pragma unroll
                for (int nf = 0; nf < 4; nf++) {
                    uint32_t b0 = Bf[nf >> 1][(nf & 1) * 2];
                    uint32_t b1 = Bf[nf >> 1][(nf & 1) * 2 + 1];
                    mma16816(acc[mf][nf][0], acc[mf][nf][1], acc[mf][nf][2], acc[mf][nf][3],
                             Af[mf][0], Af[mf][1], Af[mf][2], Af[mf][3],
                             b0, b1);
                }
        }
    }

    const int gr = lid >> 2, gc = (lid & 3) * 2;
#pragma unroll
    for (int mf = 0; mf < 4; mf++) {
        int m = m0 + mf * 16 + gr;
#pragma unroll
        for (int nf = 0; nf < 4; nf++) {
            int n = n0 + wn * 32 + nf * 8 + gc;
            *(__half2*)(C + (size_t)m * VD + n) =
                __floats2half2_rn(acc[mf][nf][0], acc[mf][nf][1]);
            *(__half2*)(C + (size_t)(m + 8) * VD + n) =
                __floats2half2_rn(acc[mf][nf][2], acc[mf][nf][3]);
        }
    }
}

// ---------------- GEMM2: 128x128x32, 3-stage, 2 CTAs/SM (proven R13 config) --
#define STG_BYTES 20480   // A tile 128*80 + B tile 128*80
#define SMEM_DYN  (3 * STG_BYTES)

__device__ __forceinline__ void load_stage(uint32_t sb, const __half* pa,
                                           const __half* pb, int m0, int n0,
                                           int kk, int K, int r, int c) {
    const __half* ga = pa + (size_t)(m0 + r) * K + kk + c * 8;
    cp16(sb + r * 80 + c * 16, ga);
    cp16(sb + (r + 64) * 80 + c * 16, ga + (size_t)64 * K);
    const __half* gb = pb + (size_t)(n0 + r) * K + kk + c * 8;
    cp16(sb + 10240 + r * 80 + c * 16, gb);
    cp16(sb + 10240 + (r + 64) * 80 + c * 16, gb + (size_t)64 * K);
}

__global__ __launch_bounds__(256, 2)
void mma_gemm2(const __half* __restrict__ A, const __half* __restrict__ B,
               __half* __restrict__ E, const float* __restrict__ rq,
               const float* __restrict__ cv,
               float* __restrict__ dr, float* __restrict__ dc) {
    extern __shared__ __align__(128) uint8_t smbuf[];
    const int tid = threadIdx.x, lid = tid & 31, wid = tid >> 5;
    const int wm = wid >> 2, wn = wid & 3;
    const int m0 = blockIdx.y * 128, n0 = blockIdx.x * 128, bz = blockIdx.z;
    const int K = VD;
    A += (size_t)bz * NQ * VD;
    B += (size_t)bz * NV * VD;

    const int T = K / 32;
    const int lr = tid >> 2, lc = tid & 3;

    float acc[4][4][4] = {};
    uint32_t sb0 = smem_u32(smbuf);

#pragma unroll
    for (int i = 0; i < 2; i++) {
        load_stage(sb0 + i * STG_BYTES, A, B, m0, n0, i * 32, K, lr, lc);
        cp_commit();
    }

    for (int i = 0; i < T; i++) {
        cp_wait1();
        __syncthreads();
        if (i + 2 < T) {
            int s = (i + 2) % 3;
            load_stage(sb0 + s * STG_BYTES, A, B, m0, n0, (i + 2) * 32, K, lr, lc);
        }
        cp_commit();
        uint32_t sb = sb0 + (i % 3) * STG_BYTES;

#pragma unroll
        for (int ks = 0; ks < 2; ks++) {
            uint32_t Af[4][4], Bf[2][4];
#pragma unroll
            for (int mf = 0; mf < 4; mf++) {
                int row = wm * 64 + mf * 16 + (lid & 15);
                int ch = ks * 2 + (lid >> 4);
                ldm4(sb + row * 80 + ch * 16,
                     Af[mf][0], Af[mf][1], Af[mf][2], Af[mf][3]);
            }
#pragma unroll
            for (int np = 0; np < 2; np++) {
                int g = lid >> 3;
                int row = wn * 32 + np * 16 + ((g >> 1) << 3) + (lid & 7);
                int ch = ks * 2 + (g & 1);
                ldm4(sb + 10240 + row * 80 + ch * 16,
                     Bf[np][0], Bf[np][1], Bf[np][2], Bf[np][3]);
            }
#pragma unroll
            for (int mf = 0; mf < 4; mf++)
#pragma unroll
                for (int nf = 0; nf < 4; nf++) {
                    uint32_t b0 = Bf[nf >> 1][(nf & 1) * 2];
                    uint32_t b1 = Bf[nf >> 1][(nf & 1) * 2 + 1];
                    mma16816(acc[mf][nf][0], acc[mf][nf][1], acc[mf][nf][2], acc[mf][nf][3],
                             Af[mf][0], Af[mf][1], Af[mf][2], Af[mf][3],
                             b0, b1);
                }
        }
    }

    const int gr = lid >> 2, gc = (lid & 3) * 2;
    float colp[4][2] = {};
    float rowp0[4], rowp1[4];
#pragma unroll
    for (int mf = 0; mf < 4; mf++) {
        int m = m0 + wm * 64 + mf * 16 + gr;
        float r0v = rq[bz * NQ + m], r1v = rq[bz * NQ + m + 8];
        float s0 = 0.f, s1 = 0.f;
#pragma unroll
        for (int nf = 0; nf < 4; nf++) {
            int n = n0 + wn * 32 + nf * 8 + gc;
            float cv0 = cv[bz * NV + n], cv1 = cv[bz * NV + n + 1];
            float e00 = exp_tanh(acc[mf][nf][0] + r0v + cv0);
            float e01 = exp_tanh(acc[mf][nf][1] + r0v + cv1);
            float e10 = exp_tanh(acc[mf][nf][2] + r1v + cv0);
            float e11 = exp_tanh(acc[mf][nf][3] + r1v + cv1);
            size_t e0 = (size_t)bz * NQ * NV + (size_t)m * NV + n;
            *(__half2*)(g_E + e0) = __floats2half2_rn(e00, e01);
            *(__half2*)(g_E + e0 + (size_t)8 * NV) = __floats2half2_rn(e10, e11);
            s0 += e00 + e01;
            s1 += e10 + e11;
            colp[nf][0] += e00 + e10;
            colp[nf][1] += e01 + e11;
        }
        rowp0[mf] = s0;
        rowp1[mf] = s1;
    }
#pragma unroll
    for (int mf = 0; mf < 4; mf++) {
        float s0 = rowp0[mf], s1 = rowp1[mf];
        s0 += __shfl_xor_sync(0xffffffffu, s0, 1);
        s0 += __shfl_xor_sync(0xffffffffu, s0, 2);
        s1 += __shfl_xor_sync(0xffffffffu, s1, 1);
        s1 += __shfl_xor_sync(0xffffffffu, s1, 2);
        if ((lid & 3) == 0) {
            int m = m0 + wm * 64 + mf * 16 + gr;
            atomicAdd(dr + bz * NQ + m, s0);
            atomicAdd(dr + bz * NQ + m + 8, s1);
        }
    }
#pragma unroll
    for (int nf = 0; nf < 4; nf++)
#pragma unroll
        for (int t = 0; t < 2; t++) {
            float s = colp[nf][t];
            s += __shfl_xor_sync(0xffffffffu, s, 4);
            s += __shfl_xor_sync(0xffffffffu, s, 8);
            s += __shfl_xor_sync(0xffffffffu, s, 16);
            colp[nf][t] = s;
        }
    if (lid < 4) {
#pragma unroll
        for (int nf = 0; nf < 4; nf++) {
            int n = n0 + wn * 32 + nf * 8 + gc;
            atomicAdd(dc + bz * NV + n, colp[nf][0]);
            atomicAdd(dc + bz * NV + n + 1, colp[nf][1]);
        }
    }
}

// ---------------- fused wq + wv: single pass over E --------------------------
__global__ __launch_bounds__(256)
void wqwv_kernel(const float* __restrict__ dr, const float* __restrict__ dc,
                 float* __restrict__ wv) {
    __shared__ float2 sdc[NV / 2];
    int b = blockIdx.y, q0 = blockIdx.x * 128;
    int tid = threadIdx.x, w = tid >> 5, lane = tid & 31;
    for (int i = tid; i < NV / 2; i += 256) {
        sdc[i].x = 1.f / dc[b * NV + 2 * i];
        sdc[i].y = 1.f / dc[b * NV + 2 * i + 1];
    }
    __syncthreads();

    float colacc[32] = {};
#pragma unroll 1
    for (int r = 0; r < 16; r++) {
        int q = q0 + w * 16 + r;
        const __half2* row = (const __half2*)(g_E + (size_t)(b * NQ + q) * NV);
        float idr = 1.f / dr[b * NQ + q];
        float s = 0.f;
#pragma unroll
        for (int j = 0; j < 16; j++) {
            int idx = lane + j * 32;
            float2 v = __half22float2(row[idx]);
            float2 d = sdc[idx];
            s += v.x * d.x + v.y * d.y;
            colacc[2 * j]     += v.x * idr;
            colacc[2 * j + 1] += v.y * idr;
        }
#pragma unroll
        for (int o = 16; o; o >>= 1) s += __shfl_xor_sync(0xffffffffu, s, o);
        if (!lane) g_wq[b * NQ + q] = s;
    }
#pragma unroll
    for (int j = 0; j < 16; j++) {
        int idx = lane + j * 32;
        atomicAdd(wv + b * NV + 2 * idx, colacc[2 * j]);
        atomicAdd(wv + b * NV + 2 * idx + 1, colacc[2 * j + 1]);
    }
}

// ------------- pools: v_hat and q_hat partials straight into out -------------
__global__ __launch_bounds__(768)
void pools_kernel(const float* __restrict__ wv, float* __restrict__ out) {
    int b = blockIdx.x, y = blockIdx.y, d = threadIdx.x;
    if (y < 4) {
        if (d < VD) {
            const __half* Vb = g_Vf + (size_t)b * NV * VD + (size_t)y * (NV / 4) * VD;
            const float* w = wv + b * NV + y * (NV / 4);
            float s = 0.f;
#pragma unroll 4
            for (int v = 0; v < NV / 4; v++) s += w[v] * __half2float(Vb[(size_t)v * VD + d]);
            atomicAdd(out + b * VD + d, s);
        }
    } else {
        int part = y - 4;
        const __half* Qb = g_Qf + (size_t)b * NQ * QD + (size_t)part * (NQ / 4) * QD;
        const float* w = g_wq + b * NQ + part * (NQ / 4);
        float s = 0.f;
#pragma unroll 4
        for (int q = 0; q < NQ / 4; q++) s += w[q] * __half2float(Qb[(size_t)q * QD + d]);
        atomicAdd(out + B_ * VD + b * QD + d, s);
    }
}

// ---------------- launch -----------------------------------------------------
extern "C" void kernel_launch(void* const* d_in, const int* in_sizes, int n_in,
                              void* d_out, int out_size) {
    const float* V  = (const float*)d_in[0];
    const float* Q  = (const float*)d_in[1];
    const float* Wq = (const float*)d_in[2];
    const float* bq = (const float*)d_in[3];
    const float* Wv = (const float*)d_in[4];
    const float* bv = (const float*)d_in[5];
    float* out = (float*)d_out;

    float *pz, *prq, *pcv;
    __half *pQf, *pVf, *pMTf, *pQMf;
    cudaGetSymbolAddress((void**)&prq, g_rq);
    cudaGetSymbolAddress((void**)&pcv, g_cv);
    cudaGetSymbolAddress((void**)&pz, g_zero);
    cudaGetSymbolAddress((void**)&pQf, g_Qf);
    cudaGetSymbolAddress((void**)&pVf, g_Vf);
    cudaGetSymbolAddress((void**)&pMTf, g_MTf);
    cudaGetSymbolAddress((void**)&pQMf, g_QMf);
    float* pdr = pz;
    float* pdc = pz + B_ * NQ;
    float* pwv = pz + B_ * NQ + B_ * NV;

    cudaFuncSetAttribute((const void*)mma_gemm1,
                         cudaFuncAttributeMaxDynamicSharedMemorySize, SMEM1_DYN);
    cudaFuncSetAttribute((const void*)mma_gemm2,
                         cudaFuncAttributeMaxDynamicSharedMemorySize, SMEM_DYN);

    // 1) a, c, s0 + zero accumulators and output
    compute_ac<<<(ZN + 1023) / 1024, 1024>>>(Wq, Wv, bq, bv, out);
    // 2) MT[v,q] = sum_h Wv[h,v] * Wq[h,q]  -> fp16 directly
    gemm_tn_kernel<<<dim3(QD / 128, VD / 128, 1), 256>>>(Wv, Wq, pMTf, HIDD, VD, QD, QD);
    // 3) fused convert + row-dot for BOTH Q and V (one launch)
    fuse_both<<<QBLOCKS + VBLOCKS, 256>>>(Q, V);
    // 4) QM = Q @ MT^T   (4th launch -> profiled; 64x128 tile, 4 CTAs/SM experiment)
    mma_gemm1<<<dim3(VD / 128, (B_ * NQ) / 64), 128, SMEM1_DYN>>>(pQf, pMTf, pQMf);
    // 5) E = exp(tanh(QM @ V^T + rq + cv)) -> fp16, + fused row/col sums
    mma_gemm2<<<dim3(NV / 128, NQ / 128, B_), 256, SMEM_DYN>>>(
        pQMf, pVf, nullptr, prq, pcv, pdr, pdc);
    // 6) fused wq + wv (one pass over E)
    wqwv_kernel<<<dim3(NQ / 128, B_), 256>>>(pdr, pdc, pwv);
    // 7) pools -> out directly
    pools_kernel<<<dim3(B_, 8), 768>>>(pwv, out);
}

// round 16
// speedup vs baseline: 1.1266x; 1.1100x over previous
#include <cuda_runtime.h>
#include <cuda_fp16.h>
#include <cstdint>

#define B_   64
#define NQ   512
#define NV   1024
#define QD   768
#define VD   512
#define HIDD 512

// ---------------- scratch (device globals; no allocation allowed) ----------
__device__ __align__(16) float g_a[QD];
__device__ __align__(16) float g_c[VD];
__device__ float g_s0;
__device__ float g_rq[B_ * NQ];
__device__ float g_cv[B_ * NV];
__device__ __align__(16) __half g_Qf[(size_t)B_ * NQ * QD];
__device__ __align__(16) __half g_Vf[(size_t)B_ * NV * VD];
__device__ __align__(16) __half g_MTf[VD * QD];
__device__ __align__(16) __half g_QMf[(size_t)B_ * NQ * VD];
__device__ __align__(16) __half g_E[(size_t)B_ * NQ * NV];
// atomic accumulators (zeroed each call by compute_ac): [dr(B*NQ) | dc(B*NV) | wv(B*NV)]
#define ZN (B_ * NQ + 2 * B_ * NV)
#define NOUT (B_ * VD + B_ * QD)
__device__ float g_zero[ZN];

// ---------------- PTX helpers (sm_80+ features only) ------------------------
__device__ __forceinline__ uint32_t smem_u32(const void* p) {
    uint32_t a;
    asm("{ .reg .u64 t; cvta.to.shared.u64 t, %1; cvt.u32.u64 %0, t; }" : "=r"(a) : "l"(p));
    return a;
}
__device__ __forceinline__ void cp16(uint32_t s, const void* g) {
    asm volatile("cp.async.cg.shared.global [%0], [%1], 16;" :: "r"(s), "l"(g));
}
__device__ __forceinline__ void cp_commit() { asm volatile("cp.async.commit_group;" ::: "memory"); }
__device__ __forceinline__ void cp_wait1()  { asm volatile("cp.async.wait_group 1;" ::: "memory"); }

__device__ __forceinline__ void ldm4(uint32_t a, uint32_t& r0, uint32_t& r1,
                                     uint32_t& r2, uint32_t& r3) {
    asm volatile("ldmatrix.sync.aligned.m8n8.x4.shared.b16 {%0,%1,%2,%3}, [%4];"
                 : "=r"(r0), "=r"(r1), "=r"(r2), "=r"(r3) : "r"(a));
}
__device__ __forceinline__ void mma16816(float& c0, float& c1, float& c2, float& c3,
                                         uint32_t a0, uint32_t a1, uint32_t a2, uint32_t a3,
                                         uint32_t b0, uint32_t b1) {
    asm volatile("mma.sync.aligned.m16n8k16.row.col.f32.f16.f16.f32 "
                 "{%0,%1,%2,%3}, {%4,%5,%6,%7}, {%8,%9}, {%0,%1,%2,%3};"
                 : "+f"(c0), "+f"(c1), "+f"(c2), "+f"(c3)
                 : "r"(a0), "r"(a1), "r"(a2), "r"(a3), "r"(b0), "r"(b1));
}
// HW tanh (sm_75+ MUFU.TANH) then exp
__device__ __forceinline__ float exp_tanh(float y) {
    float t;
    asm("tanh.approx.f32 %0, %1;" : "=f"(t) : "f"(y));
    return __expf(t);
}

// ------- precompute a, c, s0 + zero atomic accumulators AND the output -------
__global__ void compute_ac(const float* __restrict__ Wq, const float* __restrict__ Wv,
                           const float* __restrict__ bq, const float* __restrict__ bv,
                           float* __restrict__ out) {
    int t = blockIdx.x * 1024 + threadIdx.x;
    if (t < ZN) g_zero[t] = 0.f;
    if (t < NOUT) out[t] = 0.f;
    if (t < QD) {
        float s = 0.f;
        for (int h = 0; h < HIDD; h++) s += Wq[h * QD + t] * bv[h];
        g_a[t] = s;
    } else if (t < QD + VD) {
        int e = t - QD;
        float s = 0.f;
        for (int h = 0; h < HIDD; h++) s += Wv[h * VD + e] * bq[h];
        g_c[e] = s;
    } else if (t == QD + VD) {
        float s = 0.f;
        for (int h = 0; h < HIDD; h++) s += bq[h] * bv[h];
        g_s0 = s;
    }
}

// ---------------- fused fp32->fp16 convert + row-dot (Q and V in ONE launch) --
template <int K, int NF4, bool ADD_S0>
__device__ __forceinline__ void cvt_dot_row(const float* __restrict__ X,
                                            __half* __restrict__ Xf,
                                            const float* __restrict__ vec,
                                            float* __restrict__ out,
                                            int row, int lane) {
    const float4* xr = (const float4*)(X + (size_t)row * K);
    const float4* vr = (const float4*)vec;
    __half2* hr = (__half2*)(Xf + (size_t)row * K);
    float s = 0.f;
#pragma unroll
    for (int j = 0; j < NF4; j++) {
        int idx = lane + j * 32;
        float4 v = xr[idx];
        float4 a = vr[idx];
        s += v.x * a.x + v.y * a.y + v.z * a.z + v.w * a.w;
        hr[2 * idx]     = __floats2half2_rn(v.x, v.y);
        hr[2 * idx + 1] = __floats2half2_rn(v.z, v.w);
    }
#pragma unroll
    for (int o = 16; o; o >>= 1) s += __shfl_xor_sync(0xffffffffu, s, o);
    if (!lane) out[row] = s + (ADD_S0 ? g_s0 : 0.f);
}

#define QBLOCKS (B_ * NQ / 8)   // 4096
#define VBLOCKS (B_ * NV / 8)   // 8192

__global__ void fuse_both(const float* __restrict__ Q, const float* __restrict__ V) {
    int lane = threadIdx.x & 31;
    if (blockIdx.x < QBLOCKS) {
        int row = blockIdx.x * 8 + (threadIdx.x >> 5);
        cvt_dot_row<QD, QD / 128, true>(Q, g_Qf, g_a, g_rq, row, lane);
    } else {
        int row = (blockIdx.x - QBLOCKS) * 8 + (threadIdx.x >> 5);
        cvt_dot_row<VD, VD / 128, false>(V, g_Vf, g_c, g_cv, row, lane);
    }
}

// ---------------- fp32 GEMM -> fp16 out (tiny MT = Wv^T Wq) ------------------
__global__ __launch_bounds__(256)
void gemm_tn_kernel(const float* __restrict__ A, const float* __restrict__ B,
                    __half* __restrict__ C, int K, int lda, int ldb, int ldc) {
    const int BM = 128, BN = 128, BK = 8;
    const int m0 = blockIdx.y * BM, n0 = blockIdx.x * BN;
    __shared__ float As[BK][BM + 4];
    __shared__ float Bs[BK][BN + 4];
    const int tid = threadIdx.x;
    const int tx = tid & 15, ty = tid >> 4;
    float acc[8][8];
#pragma unroll
    for (int i = 0; i < 8; i++)
#pragma unroll
        for (int j = 0; j < 8; j++) acc[i][j] = 0.f;
    for (int k0 = 0; k0 < K; k0 += BK) {
        {
            int k = tid >> 5, m4 = (tid & 31) * 4;
            *(float4*)&As[k][m4] = *(const float4*)&A[(size_t)(k0 + k) * lda + m0 + m4];
        }
        {
            int k = tid >> 5, n4 = (tid & 31) * 4;
            *(float4*)&Bs[k][n4] = *(const float4*)&B[(size_t)(k0 + k) * ldb + n0 + n4];
        }
        __syncthreads();
#pragma unroll
        for (int k = 0; k < BK; k++) {
            float4 a0 = *(const float4*)&As[k][ty * 8];
            float4 a1 = *(const float4*)&As[k][ty * 8 + 4];
            float4 b0 = *(const float4*)&Bs[k][tx * 8];
            float4 b1 = *(const float4*)&Bs[k][tx * 8 + 4];
            float ar[8] = {a0.x, a0.y, a0.z, a0.w, a1.x, a1.y, a1.z, a1.w};
            float br[8] = {b0.x, b0.y, b0.z, b0.w, b1.x, b1.y, b1.z, b1.w};
#pragma unroll
            for (int i = 0; i < 8; i++)
#pragma unroll
                for (int j = 0; j < 8; j++) acc[i][j] += ar[i] * br[j];
        }
        __syncthreads();
    }
#pragma unroll
    for (int i = 0; i < 8; i++) {
        int m = m0 + ty * 8 + i;
        __half2* cptr = (__half2*)&C[(size_t)m * ldc + n0 + tx * 8];
#pragma unroll
        for (int j = 0; j < 4; j++)
            cptr[j] = __floats2half2_rn(acc[i][2 * j], acc[i][2 * j + 1]);
    }
}

// ---------------- mma.sync fp16 GEMM, 128x128x32, 3-stage, 2 CTAs/SM ---------
#define STG_BYTES 20480   // A tile 128*80 + B tile 128*80
#define SMEM_DYN  (3 * STG_BYTES)

__device__ __forceinline__ void load_stage(uint32_t sb, const __half* pa,
                                           const __half* pb, int m0, int n0,
                                           int kk, int K, int r, int c) {
    const __half* ga = pa + (size_t)(m0 + r) * K + kk + c * 8;
    cp16(sb + r * 80 + c * 16, ga);
    cp16(sb + (r + 64) * 80 + c * 16, ga + (size_t)64 * K);
    const __half* gb = pb + (size_t)(n0 + r) * K + kk + c * 8;
    cp16(sb + 10240 + r * 80 + c * 16, gb);
    cp16(sb + 10240 + (r + 64) * 80 + c * 16, gb + (size_t)64 * K);
}

// EPI=false: C = fp16(acc).  EPI=true: E=fp16(exp(tanh(acc+rq+cv))) + atomic row/col sums.
template <bool EPI>
__global__ __launch_bounds__(256, 2)
void mma_gemm(const __half* __restrict__ A, const __half* __restrict__ B,
              int K, long long sA, long long sB,
              __half* __restrict__ C, int ldc,
              __half* __restrict__ E, const float* __restrict__ rq, const float* __restrict__ cv,
              float* __restrict__ dr, float* __restrict__ dc) {
    extern __shared__ __align__(128) uint8_t smbuf[];
    const int tid = threadIdx.x, lid = tid & 31, wid = tid >> 5;
    const int wm = wid >> 2, wn = wid & 3;   // 2 x 4 warp grid
    const int m0 = blockIdx.y * 128, n0 = blockIdx.x * 128, bz = blockIdx.z;
    A += (size_t)bz * sA;
    B += (size_t)bz * sB;

    const int T = K / 32;
    const int lr = tid >> 2, lc = tid & 3;   // loader row/chunk

    float acc[4][4][4] = {};
    uint32_t sb0 = smem_u32(smbuf);

#pragma unroll
    for (int i = 0; i < 2; i++) {
        load_stage(sb0 + i * STG_BYTES, A, B, m0, n0, i * 32, K, lr, lc);
        cp_commit();
    }

    for (int i = 0; i < T; i++) {
        cp_wait1();
        __syncthreads();
        if (i + 2 < T) {
            int s = (i + 2) % 3;
            load_stage(sb0 + s * STG_BYTES, A, B, m0, n0, (i + 2) * 32, K, lr, lc);
        }
        cp_commit();
        uint32_t sb = sb0 + (i % 3) * STG_BYTES;

#pragma unroll
        for (int ks = 0; ks < 2; ks++) {
            uint32_t Af[4][4], Bf[2][4];
#pragma unroll
            for (int mf = 0; mf < 4; mf++) {
                int row = wm * 64 + mf * 16 + (lid & 15);
                int ch = ks * 2 + (lid >> 4);
                ldm4(sb + row * 80 + ch * 16,
                     Af[mf][0], Af[mf][1], Af[mf][2], Af[mf][3]);
            }
#pragma unroll
            for (int np = 0; np < 2; np++) {
                int g = lid >> 3;
                int row = wn * 32 + np * 16 + ((g >> 1) << 3) + (lid & 7);
                int ch = ks * 2 + (g & 1);
                ldm4(sb + 10240 + row * 80 + ch * 16,
                     Bf[np][0], Bf[np][1], Bf[np][2], Bf[np][3]);
            }
#pragma unroll
            for (int mf = 0; mf < 4; mf++)
#pragma unroll
                for (int nf = 0; nf < 4; nf++) {
                    uint32_t b0 = Bf[nf >> 1][(nf & 1) * 2];
                    uint32_t b1 = Bf[nf >> 1][(nf & 1) * 2 + 1];
                    mma16816(acc[mf][nf][0], acc[mf][nf][1], acc[mf][nf][2], acc[mf][nf][3],
                             Af[mf][0], Af[mf][1], Af[mf][2], Af[mf][3],
                             b0, b1);
                }
        }
    }

    // epilogue
    const int gr = lid >> 2, gc = (lid & 3) * 2;
    if (!EPI) {
#pragma unroll
        for (int mf = 0; mf < 4; mf++) {
            int m = m0 + wm * 64 + mf * 16 + gr;
#pragma unroll
            for (int nf = 0; nf < 4; nf++) {
                int n = n0 + wn * 32 + nf * 8 + gc;
                *(__half2*)(C + (size_t)m * ldc + n) =
                    __floats2half2_rn(acc[mf][nf][0], acc[mf][nf][1]);
                *(__half2*)(C + (size_t)(m + 8) * ldc + n) =
                    __floats2half2_rn(acc[mf][nf][2], acc[mf][nf][3]);
            }
        }
    } else {
        float colp[4][2] = {};
        float rowp0[4], rowp1[4];
#pragma unroll
        for (int mf = 0; mf < 4; mf++) {
            int m = m0 + wm * 64 + mf * 16 + gr;
            float r0v = rq[bz * NQ + m], r1v = rq[bz * NQ + m + 8];
            float s0 = 0.f, s1 = 0.f;
#pragma unroll
            for (int nf = 0; nf < 4; nf++) {
                int n = n0 + wn * 32 + nf * 8 + gc;
                float cv0 = cv[bz * NV + n], cv1 = cv[bz * NV + n + 1];
                float e00 = exp_tanh(acc[mf][nf][0] + r0v + cv0);
                float e01 = exp_tanh(acc[mf][nf][1] + r0v + cv1);
                float e10 = exp_tanh(acc[mf][nf][2] + r1v + cv0);
                float e11 = exp_tanh(acc[mf][nf][3] + r1v + cv1);
                size_t e0 = (size_t)bz * NQ * NV + (size_t)m * NV + n;
                *(__half2*)(E + e0) = __floats2half2_rn(e00, e01);
                *(__half2*)(E + e0 + (size_t)8 * NV) = __floats2half2_rn(e10, e11);
                s0 += e00 + e01;
                s1 += e10 + e11;
                colp[nf][0] += e00 + e10;
                colp[nf][1] += e01 + e11;
            }
            rowp0[mf] = s0;
            rowp1[mf] = s1;
        }
#pragma unroll
        for (int mf = 0; mf < 4; mf++) {
            float s0 = rowp0[mf], s1 = rowp1[mf];
            s0 += __shfl_xor_sync(0xffffffffu, s0, 1);
            s0 += __shfl_xor_sync(0xffffffffu, s0, 2);
            s1 += __shfl_xor_sync(0xffffffffu, s1, 1);
            s1 += __shfl_xor_sync(0xffffffffu, s1, 2);
            if ((lid & 3) == 0) {
                int m = m0 + wm * 64 + mf * 16 + gr;
                atomicAdd(dr + bz * NQ + m, s0);
                atomicAdd(dr + bz * NQ + m + 8, s1);
            }
        }
#pragma unroll
        for (int nf = 0; nf < 4; nf++)
#pragma unroll
            for (int t = 0; t < 2; t++) {
                float s = colp[nf][t];
                s += __shfl_xor_sync(0xffffffffu, s, 4);
                s += __shfl_xor_sync(0xffffffffu, s, 8);
                s += __shfl_xor_sync(0xffffffffu, s, 16);
                colp[nf][t] = s;
            }
        if (lid < 4) {
#pragma unroll
            for (int nf = 0; nf < 4; nf++) {
                int n = n0 + wn * 32 + nf * 8 + gc;
                atomicAdd(dc + bz * NV + n, colp[nf][0]);
                atomicAdd(dc + bz * NV + n + 1, colp[nf][1]);
            }
        }
    }
}

// ---- fused wq + wv + q_hat: single pass over E, q_hat partials into out -----
// grid (NQ/128, B_), 256 thr. Warp w handles rows q0 + w*16 .. +15.
__global__ __launch_bounds__(256)
void wqwv_kernel(const float* __restrict__ dr, const float* __restrict__ dc,
                 float* __restrict__ wv, float* __restrict__ out) {
    __shared__ float2 sdc[NV / 2];        // 4 KB
    __shared__ float qpart[QD];           // 3 KB
    int b = blockIdx.y, q0 = blockIdx.x * 128;
    int tid = threadIdx.x, w = tid >> 5, lane = tid & 31;
    for (int i = tid; i < NV / 2; i += 256) {
        sdc[i].x = 1.f / dc[b * NV + 2 * i];
        sdc[i].y = 1.f / dc[b * NV + 2 * i + 1];
    }
    for (int i = tid; i < QD; i += 256) qpart[i] = 0.f;
    __syncthreads();

    float colacc[32] = {};
    float qacc[24] = {};                  // 12 half2 lanes' worth of q_hat partials
#pragma unroll 1
    for (int r = 0; r < 16; r++) {
        int q = q0 + w * 16 + r;
        const __half2* row = (const __half2*)(g_E + (size_t)(b * NQ + q) * NV);
        float idr = 1.f / dr[b * NQ + q];
        float s = 0.f;
#pragma unroll
        for (int j = 0; j < 16; j++) {
            int idx = lane + j * 32;
            float2 v = __half22float2(row[idx]);
            float2 d = sdc[idx];
            s += v.x * d.x + v.y * d.y;
            colacc[2 * j]     += v.x * idr;
            colacc[2 * j + 1] += v.y * idr;
        }
#pragma unroll
        for (int o = 16; o; o >>= 1) s += __shfl_xor_sync(0xffffffffu, s, o);
        // all lanes now hold wq for row q; accumulate q_hat partial
        const __half2* qrow = (const __half2*)(g_Qf + (size_t)(b * NQ + q) * QD);
#pragma unroll
        for (int j = 0; j < 12; j++) {
            float2 v = __half22float2(qrow[lane + j * 32]);
            qacc[2 * j]     += s * v.x;
            qacc[2 * j + 1] += s * v.y;
        }
    }
    // wv column partials -> global atomics
#pragma unroll
    for (int j = 0; j < 16; j++) {
        int idx = lane + j * 32;
        atomicAdd(wv + b * NV + 2 * idx, colacc[2 * j]);
        atomicAdd(wv + b * NV + 2 * idx + 1, colacc[2 * j + 1]);
    }
    // q_hat partials: reduce across the 8 warps in smem, then one global flush
#pragma unroll
    for (int j = 0; j < 12; j++) {
        int d = (lane + j * 32) * 2;
        atomicAdd(&qpart[d], qacc[2 * j]);
        atomicAdd(&qpart[d + 1], qacc[2 * j + 1]);
    }
    __syncthreads();
    for (int i = tid; i < QD; i += 256)
        atomicAdd(out + B_ * VD + b * QD + i, qpart[i]);
}

// ------------- pools: v_hat partials straight into out (v_hat only) ----------
__global__ __launch_bounds__(512)
void pools_kernel(const float* __restrict__ wv, float* __restrict__ out) {
    int b = blockIdx.x, part = blockIdx.y, d = threadIdx.x;
    const __half* Vb = g_Vf + (size_t)b * NV * VD + (size_t)part * (NV / 4) * VD;
    const float* w = wv + b * NV + part * (NV / 4);
    float s = 0.f;
#pragma unroll 4
    for (int v = 0; v < NV / 4; v++) s += w[v] * __half2float(Vb[(size_t)v * VD + d]);
    atomicAdd(out + b * VD + d, s);
}

// ---------------- launch -----------------------------------------------------
extern "C" void kernel_launch(void* const* d_in, const int* in_sizes, int n_in,
                              void* d_out, int out_size) {
    const float* V  = (const float*)d_in[0];
    const float* Q  = (const float*)d_in[1];
    const float* Wq = (const float*)d_in[2];
    const float* bq = (const float*)d_in[3];
    const float* Wv = (const float*)d_in[4];
    const float* bv = (const float*)d_in[5];
    float* out = (float*)d_out;

    float *pz, *prq, *pcv;
    __half *pQf, *pVf, *pMTf, *pQMf, *pE;
    cudaGetSymbolAddress((void**)&prq, g_rq);
    cudaGetSymbolAddress((void**)&pcv, g_cv);
    cudaGetSymbolAddress((void**)&pz, g_zero);
    cudaGetSymbolAddress((void**)&pE, g_E);
    cudaGetSymbolAddress((void**)&pQf, g_Qf);
    cudaGetSymbolAddress((void**)&pVf, g_Vf);
    cudaGetSymbolAddress((void**)&pMTf, g_MTf);
    cudaGetSymbolAddress((void**)&pQMf, g_QMf);
    float* pdr = pz;
    float* pdc = pz + B_ * NQ;
    float* pwv = pz + B_ * NQ + B_ * NV;

    cudaFuncSetAttribute((const void*)mma_gemm<false>,
                         cudaFuncAttributeMaxDynamicSharedMemorySize, SMEM_DYN);
    cudaFuncSetAttribute((const void*)mma_gemm<true>,
                         cudaFuncAttributeMaxDynamicSharedMemorySize, SMEM_DYN);

    // 1) a, c, s0 + zero accumulators and output
    compute_ac<<<(ZN + 1023) / 1024, 1024>>>(Wq, Wv, bq, bv, out);
    // 2) MT[v,q] = sum_h Wv[h,v] * Wq[h,q]  -> fp16 directly
    gemm_tn_kernel<<<dim3(QD / 128, VD / 128, 1), 256>>>(Wv, Wq, pMTf, HIDD, VD, QD, QD);
    // 3) fused convert + row-dot for BOTH Q and V (one launch)
    fuse_both<<<QBLOCKS + VBLOCKS, 256>>>(Q, V);
    // 4) QM = Q @ MT^T   (4th launch -> profiled; proven R13 config)
    mma_gemm<false><<<dim3(VD / 128, (B_ * NQ) / 128, 1), 256, SMEM_DYN>>>(
        pQf, pMTf, QD, 0, 0, pQMf, VD, nullptr, nullptr, nullptr, nullptr, nullptr);
    // 5) E = exp(tanh(QM @ V^T + rq + cv)) -> fp16, + fused row/col sums
    mma_gemm<true><<<dim3(NV / 128, NQ / 128, B_), 256, SMEM_DYN>>>(
        pQMf, pVf, VD, (long long)NQ * VD, (long long)NV * VD,
        nullptr, 0, pE, prq, pcv, pdr, pdc);
    // 6) fused wq + wv + q_hat (one pass over E, q_hat partials straight into out)
    wqwv_kernel<<<dim3(NQ / 128, B_), 256>>>(pdr, pdc, pwv, out);
    // 7) pools: v_hat -> out
    pools_kernel<<<dim3(B_, 4), 512>>>(pwv, out);
}